// round 15
// baseline (speedup 1.0000x reference)
#include <cuda_runtime.h>
#include <cuda_bf16.h>
#include <math.h>

#define NN 50000
#define NE 800000
#define HD 64
#define NG 128
#define NL 3
#define MIN_D 133
#define NTILE_E16 (NE / 16)        // 50000
#define NTILE_N ((NN + 31) / 32)   // 1563

// ---------------- scratch ----------------
__device__ float g_h[NN * HD];
__device__ unsigned g_hh[NN * 32];   // h hi, packed bf16x2 per word
__device__ unsigned g_hl[NN * 32];   // h lo
__device__ float g_pos[NN * 3];
__device__ float g_agg[NN * HD];
__device__ float g_pacc[NN * 3];
__device__ float g_deg[NN];
__device__ float g_gsum[NG * HD];
__device__ float g_gcnt[NG];

__device__ __forceinline__ float silu_f(float x) { return x / (1.0f + __expf(-x)); }

__device__ __forceinline__ void mma16816(float d[4], const unsigned* a, const unsigned* b) {
    asm volatile(
        "mma.sync.aligned.m16n8k16.row.col.f32.bf16.bf16.f32 "
        "{%0,%1,%2,%3},{%4,%5,%6,%7},{%8,%9},{%0,%1,%2,%3};\n"
        : "+f"(d[0]), "+f"(d[1]), "+f"(d[2]), "+f"(d[3])
        : "r"(a[0]), "r"(a[1]), "r"(a[2]), "r"(a[3]), "r"(b[0]), "r"(b[1]));
}

__device__ __forceinline__ void ldm4(unsigned* r, unsigned addr) {
    asm volatile("ldmatrix.sync.aligned.m8n8.x4.shared.b16 {%0,%1,%2,%3}, [%4];\n"
        : "=r"(r[0]), "=r"(r[1]), "=r"(r[2]), "=r"(r[3]) : "r"(addr));
}

__device__ __forceinline__ unsigned smem_u32(const void* p) {
    return (unsigned)__cvta_generic_to_shared(p);
}

__device__ __forceinline__ void cp16(unsigned dst, const void* src) {
    asm volatile("cp.async.cg.shared.global [%0], [%1], 16;\n" :: "r"(dst), "l"(src));
}
__device__ __forceinline__ void cp_commit() {
    asm volatile("cp.async.commit_group;\n" ::: "memory");
}
__device__ __forceinline__ void cp_wait() {
    asm volatile("cp.async.wait_all;\n" ::: "memory");
}

__device__ __forceinline__ void red2(float* p, float a, float b) {
    asm volatile("red.global.add.v2.f32 [%0], {%1, %2};\n"
        :: "l"(p), "f"(a), "f"(b) : "memory");
}

__device__ __forceinline__ void split_store(float v, __nv_bfloat16* ph, __nv_bfloat16* pl) {
    __nv_bfloat16 h = __float2bfloat16(v);
    *ph = h;
    *pl = __float2bfloat16(v - __bfloat162float(h));
}

__device__ __forceinline__ void split2(float2 v, unsigned& hw, unsigned& lw) {
    __nv_bfloat162 h2, l2;
    h2.x = __float2bfloat16(v.x); l2.x = __float2bfloat16(v.x - __bfloat162float(h2.x));
    h2.y = __float2bfloat16(v.y); l2.y = __float2bfloat16(v.y - __bfloat162float(h2.y));
    hw = *(unsigned*)&h2;
    lw = *(unsigned*)&l2;
}

// M=16 k-tile, A from shared via ldmatrix: acc[8][4] += A(16x16) * W-tiles
__device__ __forceinline__ void gemm16(float (*acc)[4],
        unsigned aAddrH, unsigned aAddrL, unsigned wH, unsigned wL,
        int wgb, int ktW) {
    unsigned ah[4], al[4];
    ldm4(ah, aAddrH);
    ldm4(al, aAddrL);
#pragma unroll
    for (int grp = 0; grp < 4; grp++) {
        unsigned bh[4], bl[4];
        ldm4(bh, wH + grp * wgb + ktW * 32);
        ldm4(bl, wL + grp * wgb + ktW * 32);
        mma16816(acc[2 * grp],     ah, bh);     mma16816(acc[2 * grp],     ah, bl);     mma16816(acc[2 * grp],     al, bh);
        mma16816(acc[2 * grp + 1], ah, bh + 2); mma16816(acc[2 * grp + 1], ah, bl + 2); mma16816(acc[2 * grp + 1], al, bh + 2);
    }
}

// M=16 k-tile, A from registers
__device__ __forceinline__ void gemm16r(float (*acc)[4],
        const unsigned* ah, const unsigned* al,
        unsigned wH, unsigned wL, int wgb, int ktW) {
#pragma unroll
    for (int grp = 0; grp < 4; grp++) {
        unsigned bh[4], bl[4];
        ldm4(bh, wH + grp * wgb + ktW * 32);
        ldm4(bl, wL + grp * wgb + ktW * 32);
        mma16816(acc[2 * grp],     ah, bh);     mma16816(acc[2 * grp],     ah, bl);     mma16816(acc[2 * grp],     al, bh);
        mma16816(acc[2 * grp + 1], ah, bh + 2); mma16816(acc[2 * grp + 1], ah, bl + 2); mma16816(acc[2 * grp + 1], al, bh + 2);
    }
}

// ---------------- init ----------------
__global__ void init_kernel(const int* __restrict__ nt, const float* __restrict__ emb,
                            const float* __restrict__ pos) {
    int i = blockIdx.x * blockDim.x + threadIdx.x;
    int st = gridDim.x * blockDim.x;
    for (int j = i; j < NN * 32; j += st) {
        int node = j >> 5, w = j & 31;
        int t = nt[node];
        float2 v = *(const float2*)&emb[t * 64 + 2 * w];
        unsigned hw, lw;
        split2(v, hw, lw);
        g_hh[j] = hw; g_hl[j] = lw;
        *(float2*)&g_h[node * 64 + 2 * w] = v;
        *(float2*)&g_agg[node * 64 + 2 * w] = make_float2(0.0f, 0.0f);
    }
    for (int j = i; j < NN * 3; j += st) { g_pos[j] = pos[j]; g_pacc[j] = 0.0f; }
    for (int j = i; j < NN; j += st) g_deg[j] = 0.0f;
}

__global__ void deg_kernel(const int* __restrict__ ei) {
    int i = blockIdx.x * blockDim.x + threadIdx.x;
    int st = gridDim.x * blockDim.x;
    for (int e = i; e < NE; e += st) atomicAdd(&g_deg[ei[NE + e]], 1.0f);
}

// =====================================================================
// Edge kernel: 16 edges/warp, 768 threads (24 warps), register A-frags,
// deeper cp.async overlap, packed red.v2 scatter.
// =====================================================================
#define EDGE_SMEM_B (76800 + 24 * 5632)   // 211968

__global__ __launch_bounds__(768) void edge_kernel(
    const int* __restrict__ ei, const float* __restrict__ ea,
    const float* __restrict__ ew1, const float* __restrict__ eb1,
    const float* __restrict__ ew2, const float* __restrict__ eb2,
    const float* __restrict__ cw1, const float* __restrict__ cb1,
    const float* __restrict__ cw2, const float* __restrict__ cb2,
    int layer) {
    extern __shared__ char smb[];
    __nv_bfloat16* w1h_e = (__nv_bfloat16*)(smb + 0);
    __nv_bfloat16* w1l_e = (__nv_bfloat16*)(smb + 19456);
    __nv_bfloat16* w2h_e = (__nv_bfloat16*)(smb + 38912);
    __nv_bfloat16* w2l_e = (__nv_bfloat16*)(smb + 48128);
    __nv_bfloat16* c1h_e = (__nv_bfloat16*)(smb + 57344);
    __nv_bfloat16* c1l_e = (__nv_bfloat16*)(smb + 66560);
    float* sB1 = (float*)(smb + 75776);
    float* sB2 = sB1 + 64;
    float* sCB1 = sB2 + 64;
    float* sC2 = sCB1 + 64;

    int tid = threadIdx.x;
    const float* w1g = ew1 + layer * MIN_D * HD;
    for (int i = tid; i < 64 * 152; i += blockDim.x) {
        int n = i / 152, k = i % 152;
        float v = (k < MIN_D) ? w1g[k * 64 + n] : 0.0f;
        split_store(v, w1h_e + n * 152 + k, w1l_e + n * 152 + k);
    }
    const float* w2g = ew2 + layer * 64 * 64;
    const float* c1g = cw1 + layer * 64 * 64;
    for (int i = tid; i < 64 * 72; i += blockDim.x) {
        int n = i / 72, k = i % 72;
        float v2 = (k < 64) ? w2g[k * 64 + n] : 0.0f;
        float vc = (k < 64) ? c1g[k * 64 + n] : 0.0f;
        split_store(v2, w2h_e + n * 72 + k, w2l_e + n * 72 + k);
        split_store(vc, c1h_e + n * 72 + k, c1l_e + n * 72 + k);
    }
    for (int i = tid; i < 64; i += blockDim.x) {
        sB1[i] = eb1[layer * 64 + i];
        sB2[i] = eb2[layer * 64 + i];
        sCB1[i] = cb1[layer * 64 + i];
        sC2[i] = cw2[layer * 64 + i];
    }
    __syncthreads();
    float cb2v = cb2[layer];

    int lane = tid & 31;
    int wl = tid >> 5;
    int c = lane & 3;
    int g = lane >> 2;
    unsigned* thw = (unsigned*)(smb + 76800 + wl * 5632) + 1152;
    unsigned* tlw = thw + 128;

    unsigned sbase = smem_u32((unsigned*)(smb + 76800 + wl * 5632));
    unsigned aH = sbase + (lane & 15) * 144 + (lane >> 4) * 16;
    unsigned aL = aH + 2304;
    unsigned tbase = smem_u32(thw);
    unsigned tH = tbase + (lane & 15) * 32 + (lane >> 4) * 16;
    unsigned tL = tH + 512;
    int wr = lane & 7, whalf = (lane >> 3) & 1, wq = lane >> 4;
    unsigned w1H = smem_u32(w1h_e) + ((wq * 8 + wr) * 76) * 4 + whalf * 16;
    unsigned w1L = smem_u32(w1l_e) + ((wq * 8 + wr) * 76) * 4 + whalf * 16;
    unsigned w2H = smem_u32(w2h_e) + ((wq * 8 + wr) * 36) * 4 + whalf * 16;
    unsigned w2L = smem_u32(w2l_e) + ((wq * 8 + wr) * 36) * 4 + whalf * 16;
    unsigned c1H = smem_u32(c1h_e) + ((wq * 8 + wr) * 36) * 4 + whalf * 16;
    unsigned c1L = smem_u32(c1l_e) + ((wq * 8 + wr) * 36) * 4 + whalf * 16;

    int subrow = lane >> 3;    // 0..3
    int ck = lane & 7;         // 16B chunk within 128B row

    int warp = (blockIdx.x * blockDim.x + tid) >> 5;
    int nwarp = (gridDim.x * blockDim.x) >> 5;
    int el = lane & 15;        // edge slot within tile

    int src = 0, dst = 0;
    if (warp < NTILE_E16) {
        if (lane < 16) {
            src = ei[warp * 16 + el];
            dst = ei[NE + warp * 16 + el];
        }
#pragma unroll
        for (int t4 = 0; t4 < 4; t4++) {
            int e2 = t4 * 4 + subrow;
            int row = __shfl_sync(0xffffffffu, dst, e2);
            unsigned d = sbase + (e2 * 36 + ck * 4) * 4;
            cp16(d, &g_hh[row * 32 + ck * 4]);
            cp16(d + 2304, &g_hl[row * 32 + ck * 4]);
        }
        cp_commit();
    }

    for (int tile = warp; tile < NTILE_E16; tile += nwarp) {
        int e = tile * 16 + el;
        float4 eav = make_float4(0.f, 0.f, 0.f, 0.f);
        float rx = 0.f, ry = 0.f, rz = 0.f, d2 = 0.f;
        if (lane < 16) {
            eav = *(const float4*)(ea + (size_t)e * 4);
            rx = g_pos[dst * 3 + 0] - g_pos[src * 3 + 0];
            ry = g_pos[dst * 3 + 1] - g_pos[src * 3 + 1];
            rz = g_pos[dst * 3 + 2] - g_pos[src * 3 + 2];
            d2 = rx * rx + ry * ry + rz * rz;
        }

        int tn = tile + nwarp;
        int nsrc = src, ndst = dst;
        if (tn < NTILE_E16 && lane < 16) {
            nsrc = ei[tn * 16 + el];
            ndst = ei[NE + tn * 16 + el];
        }

        float acc[8][4];
#pragma unroll
        for (int nt = 0; nt < 8; nt++) {
            float b0 = sB1[nt * 8 + 2 * c], b1 = sB1[nt * 8 + 2 * c + 1];
            acc[nt][0] = b0; acc[nt][1] = b1;
            acc[nt][2] = b0; acc[nt][3] = b1;
        }

        // ---- wait chunk0; GEMM1 features 0..63 (h[dst]) ----
        cp_wait();
        __syncwarp();
#pragma unroll
        for (int kt = 0; kt < 3; kt++)
            gemm16(acc, aH + kt * 32, aL + kt * 32, w1H, w1L, 4864, kt);
        // kt3: hoist A-frags, then issue chunk1 early, then do kt3 MMAs
        unsigned ah3[4], al3[4];
        ldm4(ah3, aH + 96);
        ldm4(al3, aL + 96);
        __syncwarp();
#pragma unroll
        for (int t4 = 0; t4 < 4; t4++) {
            int e2 = t4 * 4 + subrow;
            int row = __shfl_sync(0xffffffffu, src, e2);
            unsigned d = sbase + (e2 * 36 + ck * 4) * 4;
            cp16(d, &g_hh[row * 32 + ck * 4]);
            cp16(d + 2304, &g_hl[row * 32 + ck * 4]);
        }
        cp_commit();
        gemm16r(acc, ah3, al3, w1H, w1L, 4864, 3);

        // tail stage + tail GEMM (covers chunk1 flight)
        if (lane < 16) {
            float tf[16];
            tf[0] = d2; tf[1] = eav.x; tf[2] = eav.y; tf[3] = eav.z; tf[4] = eav.w;
#pragma unroll
            for (int t = 5; t < 16; t++) tf[t] = 0.0f;
#pragma unroll
            for (int t = 0; t < 8; t++) {
                unsigned hw, lw2;
                split2(make_float2(tf[2 * t], tf[2 * t + 1]), hw, lw2);
                thw[lane * 8 + t] = hw;
                tlw[lane * 8 + t] = lw2;
            }
        }
        __syncwarp();
        gemm16(acc, tH, tL, w1H, w1L, 4864, 8);   // tail features 128..143

        cp_wait();
        __syncwarp();
#pragma unroll
        for (int kt = 0; kt < 3; kt++)
            gemm16(acc, aH + kt * 32, aL + kt * 32, w1H, w1L, 4864, 4 + kt);
        // kt7: hoist A-frags, then issue next tile's chunk0 early
        ldm4(ah3, aH + 96);
        ldm4(al3, aL + 96);
        __syncwarp();
        if (tn < NTILE_E16) {
#pragma unroll
            for (int t4 = 0; t4 < 4; t4++) {
                int e2 = t4 * 4 + subrow;
                int row = __shfl_sync(0xffffffffu, ndst, e2);
                unsigned d = sbase + (e2 * 36 + ck * 4) * 4;
                cp16(d, &g_hh[row * 32 + ck * 4]);
                cp16(d + 2304, &g_hl[row * 32 + ck * 4]);
            }
            cp_commit();
        }
        gemm16r(acc, ah3, al3, w1H, w1L, 4864, 7);

        // ---- m1 = silu(acc); build A-fragments in registers ----
        unsigned mh01[8], mh23[8], ml01[8], ml23[8];
#pragma unroll
        for (int nt = 0; nt < 8; nt++) {
            float v0 = silu_f(acc[nt][0]), v1 = silu_f(acc[nt][1]);
            float v2 = silu_f(acc[nt][2]), v3 = silu_f(acc[nt][3]);
            split2(make_float2(v0, v1), mh01[nt], ml01[nt]);
            split2(make_float2(v2, v3), mh23[nt], ml23[nt]);
        }

        // ---- GEMM2: m = silu(m1 @ W2 + b2), A from registers ----
        float acc2[8][4];
#pragma unroll
        for (int nt = 0; nt < 8; nt++) {
            float b0 = sB2[nt * 8 + 2 * c], b1 = sB2[nt * 8 + 2 * c + 1];
            acc2[nt][0] = b0; acc2[nt][1] = b1;
            acc2[nt][2] = b0; acc2[nt][3] = b1;
        }
#pragma unroll
        for (int kt = 0; kt < 4; kt++) {
            unsigned ah[4] = {mh01[2 * kt], mh23[2 * kt], mh01[2 * kt + 1], mh23[2 * kt + 1]};
            unsigned al[4] = {ml01[2 * kt], ml23[2 * kt], ml01[2 * kt + 1], ml23[2 * kt + 1]};
            gemm16r(acc2, ah, al, w2H, w2L, 2304, kt);
        }

        // ---- m = silu(acc2); packed red.v2 scatter; rebuild frags ----
#pragma unroll
        for (int nt = 0; nt < 8; nt++) {
            acc2[nt][0] = silu_f(acc2[nt][0]); acc2[nt][1] = silu_f(acc2[nt][1]);
            acc2[nt][2] = silu_f(acc2[nt][2]); acc2[nt][3] = silu_f(acc2[nt][3]);
            split2(make_float2(acc2[nt][0], acc2[nt][1]), mh01[nt], ml01[nt]);
            split2(make_float2(acc2[nt][2], acc2[nt][3]), mh23[nt], ml23[nt]);
        }
        {
            int drow0 = __shfl_sync(0xffffffffu, dst, g);
            int drow1 = __shfl_sync(0xffffffffu, dst, g + 8);
            float* p0b = &g_agg[drow0 * 64 + 2 * c];
            float* p1b = &g_agg[drow1 * 64 + 2 * c];
#pragma unroll
            for (int nt = 0; nt < 8; nt++) {
                red2(p0b + nt * 8, acc2[nt][0], acc2[nt][1]);
                red2(p1b + nt * 8, acc2[nt][2], acc2[nt][3]);
            }
        }

        // ---- GEMM3: coord MLP hidden, A from registers ----
        float acc3[8][4];
#pragma unroll
        for (int nt = 0; nt < 8; nt++) {
            float b0 = sCB1[nt * 8 + 2 * c], b1 = sCB1[nt * 8 + 2 * c + 1];
            acc3[nt][0] = b0; acc3[nt][1] = b1;
            acc3[nt][2] = b0; acc3[nt][3] = b1;
        }
#pragma unroll
        for (int kt = 0; kt < 4; kt++) {
            unsigned ah[4] = {mh01[2 * kt], mh23[2 * kt], mh01[2 * kt + 1], mh23[2 * kt + 1]};
            unsigned al[4] = {ml01[2 * kt], ml23[2 * kt], ml01[2 * kt + 1], ml23[2 * kt + 1]};
            gemm16r(acc3, ah, al, c1H, c1L, 2304, kt);
        }

        // ---- coord scalar + pacc atomics ----
        float p0 = 0.f, p1 = 0.f;
#pragma unroll
        for (int nt = 0; nt < 8; nt++) {
            float w0 = sC2[nt * 8 + 2 * c], w1 = sC2[nt * 8 + 2 * c + 1];
            p0 += silu_f(acc3[nt][0]) * w0 + silu_f(acc3[nt][1]) * w1;
            p1 += silu_f(acc3[nt][2]) * w0 + silu_f(acc3[nt][3]) * w1;
        }
        p0 += __shfl_xor_sync(0xffffffffu, p0, 1); p0 += __shfl_xor_sync(0xffffffffu, p0, 2);
        p1 += __shfl_xor_sync(0xffffffffu, p1, 1); p1 += __shfl_xor_sync(0xffffffffu, p1, 2);
        int srcl = (lane & 7) * 4;
        float t0 = __shfl_sync(0xffffffffu, p0, srcl);
        float t1 = __shfl_sync(0xffffffffu, p1, srcl);
        float cc = ((el < 8) ? t0 : t1) + cb2v;

        if (lane < 16) {
            atomicAdd(&g_pacc[dst * 3 + 0], rx * cc);
            atomicAdd(&g_pacc[dst * 3 + 1], ry * cc);
            atomicAdd(&g_pacc[dst * 3 + 2], rz * cc);
        }

        src = nsrc; dst = ndst;
    }
}

// =====================================================================
// Node kernel (M=32, 512 threads) — now also re-zeroes agg/pacc
// =====================================================================
#define NODE_SMEM_B (53760 + 16 * 9216)   // 201216

__device__ __forceinline__ void gemm_kt_lm32(float (*acc)[4],
        unsigned aH, unsigned aL, unsigned wH, unsigned wL,
        int wgb, int ktA, int ktW) {
    unsigned ah0[4], ah1[4], al0[4], al1[4];
    ldm4(ah0, aH + ktA * 32);
    ldm4(ah1, aH + 2304 + ktA * 32);
    ldm4(al0, aL + ktA * 32);
    ldm4(al1, aL + 2304 + ktA * 32);
#pragma unroll
    for (int grp = 0; grp < 4; grp++) {
        unsigned bh[4], bl[4];
        ldm4(bh, wH + grp * wgb + ktW * 32);
        ldm4(bl, wL + grp * wgb + ktW * 32);
        mma16816(acc[2 * grp],     ah0, bh);     mma16816(acc[2 * grp],     ah0, bl);     mma16816(acc[2 * grp],     al0, bh);
        mma16816(acc[2 * grp + 1], ah0, bh + 2); mma16816(acc[2 * grp + 1], ah0, bl + 2); mma16816(acc[2 * grp + 1], al0, bh + 2);
        mma16816(acc[8 + 2 * grp],     ah1, bh);     mma16816(acc[8 + 2 * grp],     ah1, bl);     mma16816(acc[8 + 2 * grp],     al1, bh);
        mma16816(acc[8 + 2 * grp + 1], ah1, bh + 2); mma16816(acc[8 + 2 * grp + 1], ah1, bl + 2); mma16816(acc[8 + 2 * grp + 1], al1, bh + 2);
    }
}

__device__ __forceinline__ void act_store32(float (*acc)[4], unsigned* oh, unsigned* ol,
                                            int g, int c, bool dosilu) {
#pragma unroll
    for (int mt = 0; mt < 2; mt++)
#pragma unroll
        for (int nt = 0; nt < 8; nt++) {
            float v0 = acc[mt * 8 + nt][0], v1 = acc[mt * 8 + nt][1];
            float v2 = acc[mt * 8 + nt][2], v3 = acc[mt * 8 + nt][3];
            if (dosilu) { v0 = silu_f(v0); v1 = silu_f(v1); v2 = silu_f(v2); v3 = silu_f(v3); }
            unsigned h01, l01, h23, l23;
            split2(make_float2(v0, v1), h01, l01);
            split2(make_float2(v2, v3), h23, l23);
            int w0 = (g + 16 * mt) * 36 + nt * 4 + c;
            int w1 = (g + 8 + 16 * mt) * 36 + nt * 4 + c;
            oh[w0] = h01; ol[w0] = l01;
            oh[w1] = h23; ol[w1] = l23;
        }
}

__global__ __launch_bounds__(512) void node_kernel(
    const float* __restrict__ nw1, const float* __restrict__ nb1,
    const float* __restrict__ nw2, const float* __restrict__ nb2,
    int layer) {
    extern __shared__ char smb[];
    __nv_bfloat16* w1h_e = (__nv_bfloat16*)(smb + 0);
    __nv_bfloat16* w1l_e = (__nv_bfloat16*)(smb + 17408);
    __nv_bfloat16* w2h_e = (__nv_bfloat16*)(smb + 34816);
    __nv_bfloat16* w2l_e = (__nv_bfloat16*)(smb + 44032);
    float* sB1 = (float*)(smb + 53248);
    float* sB2 = sB1 + 64;

    int tid = threadIdx.x;
    const float* w1g = nw1 + layer * 128 * 64;
    for (int i = tid; i < 64 * 136; i += blockDim.x) {
        int n = i / 136, k = i % 136;
        float v = (k < 128) ? w1g[k * 64 + n] : 0.0f;
        split_store(v, w1h_e + n * 136 + k, w1l_e + n * 136 + k);
    }
    const float* w2g = nw2 + layer * 64 * 64;
    for (int i = tid; i < 64 * 72; i += blockDim.x) {
        int n = i / 72, k = i % 72;
        float v = (k < 64) ? w2g[k * 64 + n] : 0.0f;
        split_store(v, w2h_e + n * 72 + k, w2l_e + n * 72 + k);
    }
    for (int i = tid; i < 64; i += blockDim.x) {
        sB1[i] = nb1[layer * 64 + i];
        sB2[i] = nb2[layer * 64 + i];
    }
    __syncthreads();

    int lane = tid & 31;
    int wl = tid >> 5;
    int g = lane >> 2;
    int c = lane & 3;
    unsigned* bhw = (unsigned*)(smb + 53760 + wl * 9216);
    unsigned* blw = bhw + 1152;

    unsigned sbase = smem_u32(bhw);
    unsigned aH = sbase + ((lane & 15) * 36) * 4 + (lane >> 4) * 16;
    unsigned aL = aH + 4608;
    int wr = lane & 7, whalf = (lane >> 3) & 1, wq = lane >> 4;
    unsigned w1H = smem_u32(w1h_e) + ((wq * 8 + wr) * 68) * 4 + whalf * 16;
    unsigned w1L = smem_u32(w1l_e) + ((wq * 8 + wr) * 68) * 4 + whalf * 16;
    unsigned w2H = smem_u32(w2h_e) + ((wq * 8 + wr) * 36) * 4 + whalf * 16;
    unsigned w2L = smem_u32(w2l_e) + ((wq * 8 + wr) * 36) * 4 + whalf * 16;

    int subrow = lane >> 3;
    int ck = lane & 7;

    int warp = (blockIdx.x * blockDim.x + tid) >> 5;
    int nwarp = (gridDim.x * blockDim.x) >> 5;

    for (int tile = warp; tile < NTILE_N; tile += nwarp) {
        int base = tile * 32;
        int n = base + lane;

#pragma unroll
        for (int t4 = 0; t4 < 8; t4++) {
            int e2 = t4 * 4 + subrow;
            int row = base + e2; if (row >= NN) row = NN - 1;
            unsigned d = sbase + (e2 * 36 + ck * 4) * 4;
            cp16(d, &g_hh[row * 32 + ck * 4]);
            cp16(d + 4608, &g_hl[row * 32 + ck * 4]);
        }
        cp_commit();

        if (n < NN) {
            float d = g_deg[n];
            if (d < 1.0f) d = 1.0f;
            float inv = 1.0f / d;
            g_pos[n * 3 + 0] += g_pacc[n * 3 + 0] * inv;
            g_pos[n * 3 + 1] += g_pacc[n * 3 + 1] * inv;
            g_pos[n * 3 + 2] += g_pacc[n * 3 + 2] * inv;
            g_pacc[n * 3 + 0] = 0.0f;
            g_pacc[n * 3 + 1] = 0.0f;
            g_pacc[n * 3 + 2] = 0.0f;
        }

        float acc[16][4];
#pragma unroll
        for (int mt = 0; mt < 2; mt++)
#pragma unroll
            for (int nt = 0; nt < 8; nt++) {
                float b0 = sB1[nt * 8 + 2 * c], b1 = sB1[nt * 8 + 2 * c + 1];
                acc[mt * 8 + nt][0] = b0; acc[mt * 8 + nt][1] = b1;
                acc[mt * 8 + nt][2] = b0; acc[mt * 8 + nt][3] = b1;
            }

        cp_wait();
        __syncwarp();
#pragma unroll
        for (int kt = 0; kt < 4; kt++)
            gemm_kt_lm32(acc, aH, aL, w1H, w1L, 4352, kt, kt);
        __syncwarp();

#pragma unroll 4
        for (int e2 = 0; e2 < 32; e2++) {
            int row = base + e2; if (row >= NN) row = NN - 1;
            float2 v = *(const float2*)&g_agg[row * 64 + 2 * lane];
            unsigned hw, lw2;
            split2(v, hw, lw2);
            bhw[e2 * 36 + lane] = hw;
            blw[e2 * 36 + lane] = lw2;
            *(float2*)&g_agg[row * 64 + 2 * lane] = make_float2(0.0f, 0.0f);  // re-zero for next layer
        }
        __syncwarp();
#pragma unroll
        for (int kt = 0; kt < 4; kt++)
            gemm_kt_lm32(acc, aH, aL, w1H, w1L, 4352, kt, 4 + kt);
        __syncwarp();

        act_store32(acc, bhw, blw, g, c, true);
        __syncwarp();

        float acc2[16][4];
#pragma unroll
        for (int mt = 0; mt < 2; mt++)
#pragma unroll
            for (int nt = 0; nt < 8; nt++) {
                float b0 = sB2[nt * 8 + 2 * c], b1 = sB2[nt * 8 + 2 * c + 1];
                acc2[mt * 8 + nt][0] = b0; acc2[mt * 8 + nt][1] = b1;
                acc2[mt * 8 + nt][2] = b0; acc2[mt * 8 + nt][3] = b1;
            }
#pragma unroll
        for (int kt = 0; kt < 4; kt++)
            gemm_kt_lm32(acc2, aH, aL, w2H, w2L, 2304, kt, kt);

#pragma unroll
        for (int mt = 0; mt < 2; mt++)
#pragma unroll
            for (int nt = 0; nt < 8; nt++) {
                int r0 = base + g + 16 * mt;
                int r1 = r0 + 8;
                int col = nt * 8 + 2 * c;
                if (r0 < NN) {
                    float2* p = (float2*)&g_h[r0 * 64 + col];
                    float2 o = *p;
                    o.x += acc2[mt * 8 + nt][0]; o.y += acc2[mt * 8 + nt][1];
                    *p = o;
                    unsigned hw, lw2;
                    split2(o, hw, lw2);
                    g_hh[r0 * 32 + nt * 4 + c] = hw;
                    g_hl[r0 * 32 + nt * 4 + c] = lw2;
                }
                if (r1 < NN) {
                    float2* p = (float2*)&g_h[r1 * 64 + col];
                    float2 o = *p;
                    o.x += acc2[mt * 8 + nt][2]; o.y += acc2[mt * 8 + nt][3];
                    *p = o;
                    unsigned hw, lw2;
                    split2(o, hw, lw2);
                    g_hh[r1 * 32 + nt * 4 + c] = hw;
                    g_hl[r1 * 32 + nt * 4 + c] = lw2;
                }
            }
        __syncwarp();
    }
}

// ---------------- pooling ----------------
__global__ void pool_zero_kernel() {
    int i = blockIdx.x * blockDim.x + threadIdx.x;
    int st = gridDim.x * blockDim.x;
    for (int j = i; j < NG * HD; j += st) g_gsum[j] = 0.0f;
    for (int j = i; j < NG; j += st) g_gcnt[j] = 0.0f;
}

__global__ void pool_kernel(const int* __restrict__ batch) {
    int tid = threadIdx.x;
    int lane = tid & 31;
    int warp = (blockIdx.x * blockDim.x + tid) >> 5;
    int nwarp = (gridDim.x * blockDim.x) >> 5;
    for (int n = warp; n < NN; n += nwarp) {
        int b = batch[n];
        red2(&g_gsum[b * HD + 2 * lane], g_h[n * HD + 2 * lane], g_h[n * HD + 2 * lane + 1]);
        if (lane == 0) atomicAdd(&g_gcnt[b], 1.0f);
    }
}

// ---------------- per-graph: pre-MLP, 4-qubit circuit, post-MLP ----------------
__global__ void final_kernel(const float* __restrict__ prew, const float* __restrict__ preb,
                             const float* __restrict__ qw,
                             const float* __restrict__ pw1, const float* __restrict__ pb1,
                             const float* __restrict__ pw2, const float* __restrict__ pb2,
                             float* __restrict__ out) {
    int g = threadIdx.x;
    if (g >= NG) return;
    float cnt = g_gcnt[g];
    if (cnt < 1.0f) cnt = 1.0f;
    float qin[4];
    for (int q = 0; q < 4; q++) qin[q] = preb[q];
    for (int k = 0; k < HD; k++) {
        float gv = g_gsum[g * HD + k] / cnt;
        for (int q = 0; q < 4; q++) qin[q] += gv * prew[k * 4 + q];
    }

    float pr[16], pi[16];
    for (int i = 0; i < 16; i++) { pr[i] = 0.0f; pi[i] = 0.0f; }
    pr[0] = 1.0f;

    for (int q = 0; q < 4; q++) {
        int s = 8 >> q;
        float ch = cosf(qin[q] * 0.5f);
        float sh = sinf(qin[q] * 0.5f);
        for (int i = 0; i < 16; i++) {
            if (i & s) continue;
            int j = i | s;
            float ar = pr[i], ai = pi[i], br = pr[j], bi = pi[j];
            pr[i] = ch * ar + sh * bi;  pi[i] = ch * ai - sh * br;
            pr[j] = ch * br + sh * ai;  pi[j] = ch * bi - sh * ar;
        }
    }
    for (int l = 0; l < 2; l++) {
        for (int q = 0; q < 4; q++) {
            int s = 8 >> q;
            float ch = cosf(qw[l * 4 + q] * 0.5f);
            float sh = sinf(qw[l * 4 + q] * 0.5f);
            for (int i = 0; i < 16; i++) {
                if (i & s) continue;
                int j = i | s;
                float ar = pr[i], ai = pi[i], br = pr[j], bi = pi[j];
                pr[i] = ch * ar - sh * br;  pi[i] = ch * ai - sh * bi;
                pr[j] = sh * ar + ch * br;  pi[j] = sh * ai + ch * bi;
            }
        }
        for (int q = 0; q < 4; q++) {
            int cs = 8 >> q;
            int ts = 8 >> ((q + 1) & 3);
            for (int i = 0; i < 16; i++) {
                if ((i & cs) && !(i & ts)) {
                    int j = i | ts;
                    float t;
                    t = pr[i]; pr[i] = pr[j]; pr[j] = t;
                    t = pi[i]; pi[i] = pi[j]; pi[j] = t;
                }
            }
        }
    }
    float qo[4] = {0.0f, 0.0f, 0.0f, 0.0f};
    for (int i = 0; i < 16; i++) {
        float p = pr[i] * pr[i] + pi[i] * pi[i];
        for (int q = 0; q < 4; q++) qo[q] += (i & (8 >> q)) ? -p : p;
    }

    float acc = pb2[0];
    for (int j = 0; j < HD; j++) {
        float t = pb1[j];
        for (int q = 0; q < 4; q++) t += qo[q] * pw1[q * HD + j];
        acc += silu_f(t) * pw2[j];
    }
    out[g] = acc;
}

// ---------------- launch ----------------
extern "C" void kernel_launch(void* const* d_in, const int* in_sizes, int n_in,
                              void* d_out, int out_size) {
    const int* nt = (const int*)d_in[0];
    const float* pos = (const float*)d_in[1];
    const int* ei = (const int*)d_in[2];
    const float* ea = (const float*)d_in[3];
    const int* batch = (const int*)d_in[4];
    const float* emb = (const float*)d_in[5];
    const float* ew1 = (const float*)d_in[6];
    const float* eb1 = (const float*)d_in[7];
    const float* ew2 = (const float*)d_in[8];
    const float* eb2 = (const float*)d_in[9];
    const float* cw1 = (const float*)d_in[10];
    const float* cb1 = (const float*)d_in[11];
    const float* cw2 = (const float*)d_in[12];
    const float* cb2 = (const float*)d_in[13];
    const float* nw1 = (const float*)d_in[14];
    const float* nb1 = (const float*)d_in[15];
    const float* nw2 = (const float*)d_in[16];
    const float* nb2 = (const float*)d_in[17];
    const float* prew = (const float*)d_in[18];
    const float* preb = (const float*)d_in[19];
    const float* qw = (const float*)d_in[20];
    const float* pw1 = (const float*)d_in[21];
    const float* pb1 = (const float*)d_in[22];
    const float* pw2 = (const float*)d_in[23];
    const float* pb2 = (const float*)d_in[24];
    float* out = (float*)d_out;

    cudaFuncSetAttribute(edge_kernel, cudaFuncAttributeMaxDynamicSharedMemorySize, EDGE_SMEM_B);
    cudaFuncSetAttribute(node_kernel, cudaFuncAttributeMaxDynamicSharedMemorySize, NODE_SMEM_B);

    init_kernel<<<512, 256>>>(nt, emb, pos);
    deg_kernel<<<512, 256>>>(ei);
    for (int l = 0; l < NL; l++) {
        edge_kernel<<<148, 768, EDGE_SMEM_B>>>(ei, ea, ew1, eb1, ew2, eb2,
                                               cw1, cb1, cw2, cb2, l);
        node_kernel<<<148, 512, NODE_SMEM_B>>>(nw1, nb1, nw2, nb2, l);
    }
    pool_zero_kernel<<<64, 256>>>();
    pool_kernel<<<512, 256>>>(batch);
    final_kernel<<<1, 128>>>(prew, preb, qw, pw1, pb1, pw2, pb2, out);
}

// round 17
// speedup vs baseline: 1.0928x; 1.0928x over previous
#include <cuda_runtime.h>
#include <cuda_bf16.h>
#include <math.h>

#define NN 50000
#define NE 800000
#define HD 64
#define NG 128
#define NL 3
#define MIN_D 133
#define NTILE_E16 (NE / 16)        // 50000
#define NTILE_N ((NN + 31) / 32)   // 1563

// ---------------- scratch ----------------
__device__ float g_h[NN * HD];
__device__ unsigned g_hh[NN * 32];   // h hi, packed bf16x2 per word
__device__ unsigned g_hl[NN * 32];   // h lo
__device__ float g_pos[NN * 3];
__device__ float g_agg[NN * HD];
__device__ float g_pacc[NN * 3];
__device__ float g_deg[NN];
__device__ float g_gsum[NG * HD];
__device__ float g_gcnt[NG];

__device__ __forceinline__ float silu_f(float x) { return x / (1.0f + __expf(-x)); }

__device__ __forceinline__ void mma16816(float d[4], const unsigned* a, const unsigned* b) {
    asm volatile(
        "mma.sync.aligned.m16n8k16.row.col.f32.bf16.bf16.f32 "
        "{%0,%1,%2,%3},{%4,%5,%6,%7},{%8,%9},{%0,%1,%2,%3};\n"
        : "+f"(d[0]), "+f"(d[1]), "+f"(d[2]), "+f"(d[3])
        : "r"(a[0]), "r"(a[1]), "r"(a[2]), "r"(a[3]), "r"(b[0]), "r"(b[1]));
}

__device__ __forceinline__ void ldm4(unsigned* r, unsigned addr) {
    asm volatile("ldmatrix.sync.aligned.m8n8.x4.shared.b16 {%0,%1,%2,%3}, [%4];\n"
        : "=r"(r[0]), "=r"(r[1]), "=r"(r[2]), "=r"(r[3]) : "r"(addr));
}

__device__ __forceinline__ unsigned smem_u32(const void* p) {
    return (unsigned)__cvta_generic_to_shared(p);
}

__device__ __forceinline__ void cp16(unsigned dst, const void* src) {
    asm volatile("cp.async.cg.shared.global [%0], [%1], 16;\n" :: "r"(dst), "l"(src));
}
__device__ __forceinline__ void cp_commit() {
    asm volatile("cp.async.commit_group;\n" ::: "memory");
}
__device__ __forceinline__ void cp_wait() {
    asm volatile("cp.async.wait_all;\n" ::: "memory");
}

__device__ __forceinline__ void red2(float* p, float a, float b) {
    asm volatile("red.global.add.v2.f32 [%0], {%1, %2};\n"
        :: "l"(p), "f"(a), "f"(b) : "memory");
}

__device__ __forceinline__ void split_store(float v, __nv_bfloat16* ph, __nv_bfloat16* pl) {
    __nv_bfloat16 h = __float2bfloat16(v);
    *ph = h;
    *pl = __float2bfloat16(v - __bfloat162float(h));
}

__device__ __forceinline__ void split2(float2 v, unsigned& hw, unsigned& lw) {
    __nv_bfloat162 h2, l2;
    h2.x = __float2bfloat16(v.x); l2.x = __float2bfloat16(v.x - __bfloat162float(h2.x));
    h2.y = __float2bfloat16(v.y); l2.y = __float2bfloat16(v.y - __bfloat162float(h2.y));
    hw = *(unsigned*)&h2;
    lw = *(unsigned*)&l2;
}

// M=16 k-tile, A from shared via ldmatrix: acc[8][4] += A(16x16) * W-tiles
__device__ __forceinline__ void gemm16(float (*acc)[4],
        unsigned aAddrH, unsigned aAddrL, unsigned wH, unsigned wL,
        int wgb, int ktW) {
    unsigned ah[4], al[4];
    ldm4(ah, aAddrH);
    ldm4(al, aAddrL);
#pragma unroll
    for (int grp = 0; grp < 4; grp++) {
        unsigned bh[4], bl[4];
        ldm4(bh, wH + grp * wgb + ktW * 32);
        ldm4(bl, wL + grp * wgb + ktW * 32);
        mma16816(acc[2 * grp],     ah, bh);     mma16816(acc[2 * grp],     ah, bl);     mma16816(acc[2 * grp],     al, bh);
        mma16816(acc[2 * grp + 1], ah, bh + 2); mma16816(acc[2 * grp + 1], ah, bl + 2); mma16816(acc[2 * grp + 1], al, bh + 2);
    }
}

// M=16 k-tile, A from registers
__device__ __forceinline__ void gemm16r(float (*acc)[4],
        const unsigned* ah, const unsigned* al,
        unsigned wH, unsigned wL, int wgb, int ktW) {
#pragma unroll
    for (int grp = 0; grp < 4; grp++) {
        unsigned bh[4], bl[4];
        ldm4(bh, wH + grp * wgb + ktW * 32);
        ldm4(bl, wL + grp * wgb + ktW * 32);
        mma16816(acc[2 * grp],     ah, bh);     mma16816(acc[2 * grp],     ah, bl);     mma16816(acc[2 * grp],     al, bh);
        mma16816(acc[2 * grp + 1], ah, bh + 2); mma16816(acc[2 * grp + 1], ah, bl + 2); mma16816(acc[2 * grp + 1], al, bh + 2);
    }
}

// ---------------- init ----------------
__global__ void init_kernel(const int* __restrict__ nt, const float* __restrict__ emb,
                            const float* __restrict__ pos) {
    int i = blockIdx.x * blockDim.x + threadIdx.x;
    int st = gridDim.x * blockDim.x;
    for (int j = i; j < NN * 32; j += st) {
        int node = j >> 5, w = j & 31;
        int t = nt[node];
        float2 v = *(const float2*)&emb[t * 64 + 2 * w];
        unsigned hw, lw;
        split2(v, hw, lw);
        g_hh[j] = hw; g_hl[j] = lw;
        *(float2*)&g_h[node * 64 + 2 * w] = v;
        *(float2*)&g_agg[node * 64 + 2 * w] = make_float2(0.0f, 0.0f);
    }
    for (int j = i; j < NN * 3; j += st) { g_pos[j] = pos[j]; g_pacc[j] = 0.0f; }
    for (int j = i; j < NN; j += st) g_deg[j] = 0.0f;
}

__global__ void deg_kernel(const int* __restrict__ ei) {
    int i = blockIdx.x * blockDim.x + threadIdx.x;
    int st = gridDim.x * blockDim.x;
    for (int e = i; e < NE; e += st) atomicAdd(&g_deg[ei[NE + e]], 1.0f);
}

// =====================================================================
// Edge kernel: 16 edges/warp, 768 threads (24 warps), register A-frags,
// deeper cp.async overlap, packed red.v2 scatter.
// =====================================================================
#define EDGE_SMEM_B (76800 + 24 * 5632)   // 211968

__global__ __launch_bounds__(768) void edge_kernel(
    const int* __restrict__ ei, const float* __restrict__ ea,
    const float* __restrict__ ew1, const float* __restrict__ eb1,
    const float* __restrict__ ew2, const float* __restrict__ eb2,
    const float* __restrict__ cw1, const float* __restrict__ cb1,
    const float* __restrict__ cw2, const float* __restrict__ cb2,
    int layer) {
    extern __shared__ char smb[];
    __nv_bfloat16* w1h_e = (__nv_bfloat16*)(smb + 0);
    __nv_bfloat16* w1l_e = (__nv_bfloat16*)(smb + 19456);
    __nv_bfloat16* w2h_e = (__nv_bfloat16*)(smb + 38912);
    __nv_bfloat16* w2l_e = (__nv_bfloat16*)(smb + 48128);
    __nv_bfloat16* c1h_e = (__nv_bfloat16*)(smb + 57344);
    __nv_bfloat16* c1l_e = (__nv_bfloat16*)(smb + 66560);
    float* sB1 = (float*)(smb + 75776);
    float* sB2 = sB1 + 64;
    float* sCB1 = sB2 + 64;
    float* sC2 = sCB1 + 64;

    int tid = threadIdx.x;
    const float* w1g = ew1 + layer * MIN_D * HD;
    for (int i = tid; i < 64 * 152; i += blockDim.x) {
        int n = i / 152, k = i % 152;
        float v = (k < MIN_D) ? w1g[k * 64 + n] : 0.0f;
        split_store(v, w1h_e + n * 152 + k, w1l_e + n * 152 + k);
    }
    const float* w2g = ew2 + layer * 64 * 64;
    const float* c1g = cw1 + layer * 64 * 64;
    for (int i = tid; i < 64 * 72; i += blockDim.x) {
        int n = i / 72, k = i % 72;
        float v2 = (k < 64) ? w2g[k * 64 + n] : 0.0f;
        float vc = (k < 64) ? c1g[k * 64 + n] : 0.0f;
        split_store(v2, w2h_e + n * 72 + k, w2l_e + n * 72 + k);
        split_store(vc, c1h_e + n * 72 + k, c1l_e + n * 72 + k);
    }
    for (int i = tid; i < 64; i += blockDim.x) {
        sB1[i] = eb1[layer * 64 + i];
        sB2[i] = eb2[layer * 64 + i];
        sCB1[i] = cb1[layer * 64 + i];
        sC2[i] = cw2[layer * 64 + i];
    }
    __syncthreads();
    float cb2v = cb2[layer];

    int lane = tid & 31;
    int wl = tid >> 5;
    int c = lane & 3;
    int g = lane >> 2;
    unsigned* thw = (unsigned*)(smb + 76800 + wl * 5632) + 1152;
    unsigned* tlw = thw + 128;

    unsigned sbase = smem_u32((unsigned*)(smb + 76800 + wl * 5632));
    unsigned aH = sbase + (lane & 15) * 144 + (lane >> 4) * 16;
    unsigned aL = aH + 2304;
    unsigned tbase = smem_u32(thw);
    unsigned tH = tbase + (lane & 15) * 32 + (lane >> 4) * 16;
    unsigned tL = tH + 512;
    int wr = lane & 7, whalf = (lane >> 3) & 1, wq = lane >> 4;
    unsigned w1H = smem_u32(w1h_e) + ((wq * 8 + wr) * 76) * 4 + whalf * 16;
    unsigned w1L = smem_u32(w1l_e) + ((wq * 8 + wr) * 76) * 4 + whalf * 16;
    unsigned w2H = smem_u32(w2h_e) + ((wq * 8 + wr) * 36) * 4 + whalf * 16;
    unsigned w2L = smem_u32(w2l_e) + ((wq * 8 + wr) * 36) * 4 + whalf * 16;
    unsigned c1H = smem_u32(c1h_e) + ((wq * 8 + wr) * 36) * 4 + whalf * 16;
    unsigned c1L = smem_u32(c1l_e) + ((wq * 8 + wr) * 36) * 4 + whalf * 16;

    int subrow = lane >> 3;    // 0..3
    int ck = lane & 7;         // 16B chunk within 128B row

    int warp = (blockIdx.x * blockDim.x + tid) >> 5;
    int nwarp = (gridDim.x * blockDim.x) >> 5;
    int el = lane & 15;        // edge slot within tile

    int src = 0, dst = 0;
    if (warp < NTILE_E16) {
        if (lane < 16) {
            src = ei[warp * 16 + el];
            dst = ei[NE + warp * 16 + el];
        }
#pragma unroll
        for (int t4 = 0; t4 < 4; t4++) {
            int e2 = t4 * 4 + subrow;
            int row = __shfl_sync(0xffffffffu, dst, e2);
            unsigned d = sbase + (e2 * 36 + ck * 4) * 4;
            cp16(d, &g_hh[row * 32 + ck * 4]);
            cp16(d + 2304, &g_hl[row * 32 + ck * 4]);
        }
        cp_commit();
    }

    for (int tile = warp; tile < NTILE_E16; tile += nwarp) {
        int e = tile * 16 + el;
        float4 eav = make_float4(0.f, 0.f, 0.f, 0.f);
        float rx = 0.f, ry = 0.f, rz = 0.f, d2 = 0.f;
        if (lane < 16) {
            eav = *(const float4*)(ea + (size_t)e * 4);
            rx = g_pos[dst * 3 + 0] - g_pos[src * 3 + 0];
            ry = g_pos[dst * 3 + 1] - g_pos[src * 3 + 1];
            rz = g_pos[dst * 3 + 2] - g_pos[src * 3 + 2];
            d2 = rx * rx + ry * ry + rz * rz;
        }

        int tn = tile + nwarp;
        int nsrc = src, ndst = dst;
        if (tn < NTILE_E16 && lane < 16) {
            nsrc = ei[tn * 16 + el];
            ndst = ei[NE + tn * 16 + el];
        }

        float acc[8][4];
#pragma unroll
        for (int nt = 0; nt < 8; nt++) {
            float b0 = sB1[nt * 8 + 2 * c], b1 = sB1[nt * 8 + 2 * c + 1];
            acc[nt][0] = b0; acc[nt][1] = b1;
            acc[nt][2] = b0; acc[nt][3] = b1;
        }

        // ---- wait chunk0; GEMM1 features 0..63 (h[dst]) ----
        cp_wait();
        __syncwarp();
#pragma unroll
        for (int kt = 0; kt < 3; kt++)
            gemm16(acc, aH + kt * 32, aL + kt * 32, w1H, w1L, 4864, kt);
        // kt3: hoist A-frags, then issue chunk1 early, then do kt3 MMAs
        unsigned ah3[4], al3[4];
        ldm4(ah3, aH + 96);
        ldm4(al3, aL + 96);
        __syncwarp();
#pragma unroll
        for (int t4 = 0; t4 < 4; t4++) {
            int e2 = t4 * 4 + subrow;
            int row = __shfl_sync(0xffffffffu, src, e2);
            unsigned d = sbase + (e2 * 36 + ck * 4) * 4;
            cp16(d, &g_hh[row * 32 + ck * 4]);
            cp16(d + 2304, &g_hl[row * 32 + ck * 4]);
        }
        cp_commit();
        gemm16r(acc, ah3, al3, w1H, w1L, 4864, 3);

        // tail stage + tail GEMM (covers chunk1 flight)
        if (lane < 16) {
            float tf[16];
            tf[0] = d2; tf[1] = eav.x; tf[2] = eav.y; tf[3] = eav.z; tf[4] = eav.w;
#pragma unroll
            for (int t = 5; t < 16; t++) tf[t] = 0.0f;
#pragma unroll
            for (int t = 0; t < 8; t++) {
                unsigned hw, lw2;
                split2(make_float2(tf[2 * t], tf[2 * t + 1]), hw, lw2);
                thw[lane * 8 + t] = hw;
                tlw[lane * 8 + t] = lw2;
            }
        }
        __syncwarp();
        gemm16(acc, tH, tL, w1H, w1L, 4864, 8);   // tail features 128..143

        cp_wait();
        __syncwarp();
#pragma unroll
        for (int kt = 0; kt < 3; kt++)
            gemm16(acc, aH + kt * 32, aL + kt * 32, w1H, w1L, 4864, 4 + kt);
        // kt7: hoist A-frags, then issue next tile's chunk0 early
        ldm4(ah3, aH + 96);
        ldm4(al3, aL + 96);
        __syncwarp();
        if (tn < NTILE_E16) {
#pragma unroll
            for (int t4 = 0; t4 < 4; t4++) {
                int e2 = t4 * 4 + subrow;
                int row = __shfl_sync(0xffffffffu, ndst, e2);
                unsigned d = sbase + (e2 * 36 + ck * 4) * 4;
                cp16(d, &g_hh[row * 32 + ck * 4]);
                cp16(d + 2304, &g_hl[row * 32 + ck * 4]);
            }
            cp_commit();
        }
        gemm16r(acc, ah3, al3, w1H, w1L, 4864, 7);

        // ---- m1 = silu(acc); build A-fragments in registers ----
        unsigned mh01[8], mh23[8], ml01[8], ml23[8];
#pragma unroll
        for (int nt = 0; nt < 8; nt++) {
            float v0 = silu_f(acc[nt][0]), v1 = silu_f(acc[nt][1]);
            float v2 = silu_f(acc[nt][2]), v3 = silu_f(acc[nt][3]);
            split2(make_float2(v0, v1), mh01[nt], ml01[nt]);
            split2(make_float2(v2, v3), mh23[nt], ml23[nt]);
        }

        // ---- GEMM2: m = silu(m1 @ W2 + b2), A from registers ----
        float acc2[8][4];
#pragma unroll
        for (int nt = 0; nt < 8; nt++) {
            float b0 = sB2[nt * 8 + 2 * c], b1 = sB2[nt * 8 + 2 * c + 1];
            acc2[nt][0] = b0; acc2[nt][1] = b1;
            acc2[nt][2] = b0; acc2[nt][3] = b1;
        }
#pragma unroll
        for (int kt = 0; kt < 4; kt++) {
            unsigned ah[4] = {mh01[2 * kt], mh23[2 * kt], mh01[2 * kt + 1], mh23[2 * kt + 1]};
            unsigned al[4] = {ml01[2 * kt], ml23[2 * kt], ml01[2 * kt + 1], ml23[2 * kt + 1]};
            gemm16r(acc2, ah, al, w2H, w2L, 2304, kt);
        }

        // ---- m = silu(acc2); packed red.v2 scatter; rebuild frags ----
#pragma unroll
        for (int nt = 0; nt < 8; nt++) {
            acc2[nt][0] = silu_f(acc2[nt][0]); acc2[nt][1] = silu_f(acc2[nt][1]);
            acc2[nt][2] = silu_f(acc2[nt][2]); acc2[nt][3] = silu_f(acc2[nt][3]);
            split2(make_float2(acc2[nt][0], acc2[nt][1]), mh01[nt], ml01[nt]);
            split2(make_float2(acc2[nt][2], acc2[nt][3]), mh23[nt], ml23[nt]);
        }
        {
            int drow0 = __shfl_sync(0xffffffffu, dst, g);
            int drow1 = __shfl_sync(0xffffffffu, dst, g + 8);
            float* p0b = &g_agg[drow0 * 64 + 2 * c];
            float* p1b = &g_agg[drow1 * 64 + 2 * c];
#pragma unroll
            for (int nt = 0; nt < 8; nt++) {
                red2(p0b + nt * 8, acc2[nt][0], acc2[nt][1]);
                red2(p1b + nt * 8, acc2[nt][2], acc2[nt][3]);
            }
        }

        // ---- GEMM3: coord MLP hidden, A from registers ----
        float acc3[8][4];
#pragma unroll
        for (int nt = 0; nt < 8; nt++) {
            float b0 = sCB1[nt * 8 + 2 * c], b1 = sCB1[nt * 8 + 2 * c + 1];
            acc3[nt][0] = b0; acc3[nt][1] = b1;
            acc3[nt][2] = b0; acc3[nt][3] = b1;
        }
#pragma unroll
        for (int kt = 0; kt < 4; kt++) {
            unsigned ah[4] = {mh01[2 * kt], mh23[2 * kt], mh01[2 * kt + 1], mh23[2 * kt + 1]};
            unsigned al[4] = {ml01[2 * kt], ml23[2 * kt], ml01[2 * kt + 1], ml23[2 * kt + 1]};
            gemm16r(acc3, ah, al, c1H, c1L, 2304, kt);
        }

        // ---- coord scalar + pacc atomics ----
        float p0 = 0.f, p1 = 0.f;
#pragma unroll
        for (int nt = 0; nt < 8; nt++) {
            float w0 = sC2[nt * 8 + 2 * c], w1 = sC2[nt * 8 + 2 * c + 1];
            p0 += silu_f(acc3[nt][0]) * w0 + silu_f(acc3[nt][1]) * w1;
            p1 += silu_f(acc3[nt][2]) * w0 + silu_f(acc3[nt][3]) * w1;
        }
        p0 += __shfl_xor_sync(0xffffffffu, p0, 1); p0 += __shfl_xor_sync(0xffffffffu, p0, 2);
        p1 += __shfl_xor_sync(0xffffffffu, p1, 1); p1 += __shfl_xor_sync(0xffffffffu, p1, 2);
        int srcl = (lane & 7) * 4;
        float t0 = __shfl_sync(0xffffffffu, p0, srcl);
        float t1 = __shfl_sync(0xffffffffu, p1, srcl);
        float cc = ((el < 8) ? t0 : t1) + cb2v;

        if (lane < 16) {
            atomicAdd(&g_pacc[dst * 3 + 0], rx * cc);
            atomicAdd(&g_pacc[dst * 3 + 1], ry * cc);
            atomicAdd(&g_pacc[dst * 3 + 2], rz * cc);
        }

        src = nsrc; dst = ndst;
    }
}

// =====================================================================
// Node kernel (M=32, 512 threads). agg re-zero moved to tile epilogue
// (independent zero-stores; no load->store same-address coupling).
// =====================================================================
#define NODE_SMEM_B (53760 + 16 * 9216)   // 201216

__device__ __forceinline__ void gemm_kt_lm32(float (*acc)[4],
        unsigned aH, unsigned aL, unsigned wH, unsigned wL,
        int wgb, int ktA, int ktW) {
    unsigned ah0[4], ah1[4], al0[4], al1[4];
    ldm4(ah0, aH + ktA * 32);
    ldm4(ah1, aH + 2304 + ktA * 32);
    ldm4(al0, aL + ktA * 32);
    ldm4(al1, aL + 2304 + ktA * 32);
#pragma unroll
    for (int grp = 0; grp < 4; grp++) {
        unsigned bh[4], bl[4];
        ldm4(bh, wH + grp * wgb + ktW * 32);
        ldm4(bl, wL + grp * wgb + ktW * 32);
        mma16816(acc[2 * grp],     ah0, bh);     mma16816(acc[2 * grp],     ah0, bl);     mma16816(acc[2 * grp],     al0, bh);
        mma16816(acc[2 * grp + 1], ah0, bh + 2); mma16816(acc[2 * grp + 1], ah0, bl + 2); mma16816(acc[2 * grp + 1], al0, bh + 2);
        mma16816(acc[8 + 2 * grp],     ah1, bh);     mma16816(acc[8 + 2 * grp],     ah1, bl);     mma16816(acc[8 + 2 * grp],     al1, bh);
        mma16816(acc[8 + 2 * grp + 1], ah1, bh + 2); mma16816(acc[8 + 2 * grp + 1], ah1, bl + 2); mma16816(acc[8 + 2 * grp + 1], al1, bh + 2);
    }
}

__device__ __forceinline__ void act_store32(float (*acc)[4], unsigned* oh, unsigned* ol,
                                            int g, int c, bool dosilu) {
#pragma unroll
    for (int mt = 0; mt < 2; mt++)
#pragma unroll
        for (int nt = 0; nt < 8; nt++) {
            float v0 = acc[mt * 8 + nt][0], v1 = acc[mt * 8 + nt][1];
            float v2 = acc[mt * 8 + nt][2], v3 = acc[mt * 8 + nt][3];
            if (dosilu) { v0 = silu_f(v0); v1 = silu_f(v1); v2 = silu_f(v2); v3 = silu_f(v3); }
            unsigned h01, l01, h23, l23;
            split2(make_float2(v0, v1), h01, l01);
            split2(make_float2(v2, v3), h23, l23);
            int w0 = (g + 16 * mt) * 36 + nt * 4 + c;
            int w1 = (g + 8 + 16 * mt) * 36 + nt * 4 + c;
            oh[w0] = h01; ol[w0] = l01;
            oh[w1] = h23; ol[w1] = l23;
        }
}

__global__ __launch_bounds__(512) void node_kernel(
    const float* __restrict__ nw1, const float* __restrict__ nb1,
    const float* __restrict__ nw2, const float* __restrict__ nb2,
    int layer) {
    extern __shared__ char smb[];
    __nv_bfloat16* w1h_e = (__nv_bfloat16*)(smb + 0);
    __nv_bfloat16* w1l_e = (__nv_bfloat16*)(smb + 17408);
    __nv_bfloat16* w2h_e = (__nv_bfloat16*)(smb + 34816);
    __nv_bfloat16* w2l_e = (__nv_bfloat16*)(smb + 44032);
    float* sB1 = (float*)(smb + 53248);
    float* sB2 = sB1 + 64;

    int tid = threadIdx.x;
    const float* w1g = nw1 + layer * 128 * 64;
    for (int i = tid; i < 64 * 136; i += blockDim.x) {
        int n = i / 136, k = i % 136;
        float v = (k < 128) ? w1g[k * 64 + n] : 0.0f;
        split_store(v, w1h_e + n * 136 + k, w1l_e + n * 136 + k);
    }
    const float* w2g = nw2 + layer * 64 * 64;
    for (int i = tid; i < 64 * 72; i += blockDim.x) {
        int n = i / 72, k = i % 72;
        float v = (k < 64) ? w2g[k * 64 + n] : 0.0f;
        split_store(v, w2h_e + n * 72 + k, w2l_e + n * 72 + k);
    }
    for (int i = tid; i < 64; i += blockDim.x) {
        sB1[i] = nb1[layer * 64 + i];
        sB2[i] = nb2[layer * 64 + i];
    }
    __syncthreads();

    int lane = tid & 31;
    int wl = tid >> 5;
    int g = lane >> 2;
    int c = lane & 3;
    unsigned* bhw = (unsigned*)(smb + 53760 + wl * 9216);
    unsigned* blw = bhw + 1152;

    unsigned sbase = smem_u32(bhw);
    unsigned aH = sbase + ((lane & 15) * 36) * 4 + (lane >> 4) * 16;
    unsigned aL = aH + 4608;
    int wr = lane & 7, whalf = (lane >> 3) & 1, wq = lane >> 4;
    unsigned w1H = smem_u32(w1h_e) + ((wq * 8 + wr) * 68) * 4 + whalf * 16;
    unsigned w1L = smem_u32(w1l_e) + ((wq * 8 + wr) * 68) * 4 + whalf * 16;
    unsigned w2H = smem_u32(w2h_e) + ((wq * 8 + wr) * 36) * 4 + whalf * 16;
    unsigned w2L = smem_u32(w2l_e) + ((wq * 8 + wr) * 36) * 4 + whalf * 16;

    int subrow = lane >> 3;
    int ck = lane & 7;

    int warp = (blockIdx.x * blockDim.x + tid) >> 5;
    int nwarp = (gridDim.x * blockDim.x) >> 5;

    for (int tile = warp; tile < NTILE_N; tile += nwarp) {
        int base = tile * 32;
        int n = base + lane;

#pragma unroll
        for (int t4 = 0; t4 < 8; t4++) {
            int e2 = t4 * 4 + subrow;
            int row = base + e2; if (row >= NN) row = NN - 1;
            unsigned d = sbase + (e2 * 36 + ck * 4) * 4;
            cp16(d, &g_hh[row * 32 + ck * 4]);
            cp16(d + 4608, &g_hl[row * 32 + ck * 4]);
        }
        cp_commit();

        if (n < NN) {
            float d = g_deg[n];
            if (d < 1.0f) d = 1.0f;
            float inv = 1.0f / d;
            g_pos[n * 3 + 0] += g_pacc[n * 3 + 0] * inv;
            g_pos[n * 3 + 1] += g_pacc[n * 3 + 1] * inv;
            g_pos[n * 3 + 2] += g_pacc[n * 3 + 2] * inv;
        }

        float acc[16][4];
#pragma unroll
        for (int mt = 0; mt < 2; mt++)
#pragma unroll
            for (int nt = 0; nt < 8; nt++) {
                float b0 = sB1[nt * 8 + 2 * c], b1 = sB1[nt * 8 + 2 * c + 1];
                acc[mt * 8 + nt][0] = b0; acc[mt * 8 + nt][1] = b1;
                acc[mt * 8 + nt][2] = b0; acc[mt * 8 + nt][3] = b1;
            }

        cp_wait();
        __syncwarp();
#pragma unroll
        for (int kt = 0; kt < 4; kt++)
            gemm_kt_lm32(acc, aH, aL, w1H, w1L, 4352, kt, kt);
        __syncwarp();

        // stage agg (pure read -> split -> STS; no same-address stores here)
#pragma unroll 4
        for (int e2 = 0; e2 < 32; e2++) {
            int row = base + e2; if (row >= NN) row = NN - 1;
            float2 v = *(const float2*)&g_agg[row * 64 + 2 * lane];
            unsigned hw, lw2;
            split2(v, hw, lw2);
            bhw[e2 * 36 + lane] = hw;
            blw[e2 * 36 + lane] = lw2;
        }
        __syncwarp();
#pragma unroll
        for (int kt = 0; kt < 4; kt++)
            gemm_kt_lm32(acc, aH, aL, w1H, w1L, 4352, kt, 4 + kt);
        __syncwarp();

        act_store32(acc, bhw, blw, g, c, true);
        __syncwarp();

        float acc2[16][4];
#pragma unroll
        for (int mt = 0; mt < 2; mt++)
#pragma unroll
            for (int nt = 0; nt < 8; nt++) {
                float b0 = sB2[nt * 8 + 2 * c], b1 = sB2[nt * 8 + 2 * c + 1];
                acc2[mt * 8 + nt][0] = b0; acc2[mt * 8 + nt][1] = b1;
                acc2[mt * 8 + nt][2] = b0; acc2[mt * 8 + nt][3] = b1;
            }
#pragma unroll
        for (int kt = 0; kt < 4; kt++)
            gemm_kt_lm32(acc2, aH, aL, w2H, w2L, 2304, kt, kt);

#pragma unroll
        for (int mt = 0; mt < 2; mt++)
#pragma unroll
            for (int nt = 0; nt < 8; nt++) {
                int r0 = base + g + 16 * mt;
                int r1 = r0 + 8;
                int col = nt * 8 + 2 * c;
                if (r0 < NN) {
                    float2* p = (float2*)&g_h[r0 * 64 + col];
                    float2 o = *p;
                    o.x += acc2[mt * 8 + nt][0]; o.y += acc2[mt * 8 + nt][1];
                    *p = o;
                    unsigned hw, lw2;
                    split2(o, hw, lw2);
                    g_hh[r0 * 32 + nt * 4 + c] = hw;
                    g_hl[r0 * 32 + nt * 4 + c] = lw2;
                }
                if (r1 < NN) {
                    float2* p = (float2*)&g_h[r1 * 64 + col];
                    float2 o = *p;
                    o.x += acc2[mt * 8 + nt][2]; o.y += acc2[mt * 8 + nt][3];
                    *p = o;
                    unsigned hw, lw2;
                    split2(o, hw, lw2);
                    g_hh[r1 * 32 + nt * 4 + c] = hw;
                    g_hl[r1 * 32 + nt * 4 + c] = lw2;
                }
            }

        // ---- tile epilogue: re-zero agg + pacc (independent stores) ----
#pragma unroll 4
        for (int e2 = 0; e2 < 32; e2++) {
            int row = base + e2;
            if (row < NN)
                *(float2*)&g_agg[row * 64 + 2 * lane] = make_float2(0.0f, 0.0f);
        }
        if (n < NN) {
            g_pacc[n * 3 + 0] = 0.0f;
            g_pacc[n * 3 + 1] = 0.0f;
            g_pacc[n * 3 + 2] = 0.0f;
        }
        __syncwarp();
    }
}

// ---------------- pooling ----------------
__global__ void pool_zero_kernel() {
    int i = blockIdx.x * blockDim.x + threadIdx.x;
    int st = gridDim.x * blockDim.x;
    for (int j = i; j < NG * HD; j += st) g_gsum[j] = 0.0f;
    for (int j = i; j < NG; j += st) g_gcnt[j] = 0.0f;
}

__global__ void pool_kernel(const int* __restrict__ batch) {
    int tid = threadIdx.x;
    int lane = tid & 31;
    int warp = (blockIdx.x * blockDim.x + tid) >> 5;
    int nwarp = (gridDim.x * blockDim.x) >> 5;
    for (int n = warp; n < NN; n += nwarp) {
        int b = batch[n];
        red2(&g_gsum[b * HD + 2 * lane], g_h[n * HD + 2 * lane], g_h[n * HD + 2 * lane + 1]);
        if (lane == 0) atomicAdd(&g_gcnt[b], 1.0f);
    }
}

// ---------------- per-graph: pre-MLP, 4-qubit circuit, post-MLP ----------------
__global__ void final_kernel(const float* __restrict__ prew, const float* __restrict__ preb,
                             const float* __restrict__ qw,
                             const float* __restrict__ pw1, const float* __restrict__ pb1,
                             const float* __restrict__ pw2, const float* __restrict__ pb2,
                             float* __restrict__ out) {
    int g = threadIdx.x;
    if (g >= NG) return;
    float cnt = g_gcnt[g];
    if (cnt < 1.0f) cnt = 1.0f;
    float qin[4];
    for (int q = 0; q < 4; q++) qin[q] = preb[q];
    for (int k = 0; k < HD; k++) {
        float gv = g_gsum[g * HD + k] / cnt;
        for (int q = 0; q < 4; q++) qin[q] += gv * prew[k * 4 + q];
    }

    float pr[16], pi[16];
    for (int i = 0; i < 16; i++) { pr[i] = 0.0f; pi[i] = 0.0f; }
    pr[0] = 1.0f;

    for (int q = 0; q < 4; q++) {
        int s = 8 >> q;
        float ch = cosf(qin[q] * 0.5f);
        float sh = sinf(qin[q] * 0.5f);
        for (int i = 0; i < 16; i++) {
            if (i & s) continue;
            int j = i | s;
            float ar = pr[i], ai = pi[i], br = pr[j], bi = pi[j];
            pr[i] = ch * ar + sh * bi;  pi[i] = ch * ai - sh * br;
            pr[j] = ch * br + sh * ai;  pi[j] = ch * bi - sh * ar;
        }
    }
    for (int l = 0; l < 2; l++) {
        for (int q = 0; q < 4; q++) {
            int s = 8 >> q;
            float ch = cosf(qw[l * 4 + q] * 0.5f);
            float sh = sinf(qw[l * 4 + q] * 0.5f);
            for (int i = 0; i < 16; i++) {
                if (i & s) continue;
                int j = i | s;
                float ar = pr[i], ai = pi[i], br = pr[j], bi = pi[j];
                pr[i] = ch * ar - sh * br;  pi[i] = ch * ai - sh * bi;
                pr[j] = sh * ar + ch * br;  pi[j] = sh * ai + ch * bi;
            }
        }
        for (int q = 0; q < 4; q++) {
            int cs = 8 >> q;
            int ts = 8 >> ((q + 1) & 3);
            for (int i = 0; i < 16; i++) {
                if ((i & cs) && !(i & ts)) {
                    int j = i | ts;
                    float t;
                    t = pr[i]; pr[i] = pr[j]; pr[j] = t;
                    t = pi[i]; pi[i] = pi[j]; pi[j] = t;
                }
            }
        }
    }
    float qo[4] = {0.0f, 0.0f, 0.0f, 0.0f};
    for (int i = 0; i < 16; i++) {
        float p = pr[i] * pr[i] + pi[i] * pi[i];
        for (int q = 0; q < 4; q++) qo[q] += (i & (8 >> q)) ? -p : p;
    }

    float acc = pb2[0];
    for (int j = 0; j < HD; j++) {
        float t = pb1[j];
        for (int q = 0; q < 4; q++) t += qo[q] * pw1[q * HD + j];
        acc += silu_f(t) * pw2[j];
    }
    out[g] = acc;
}

// ---------------- launch ----------------
extern "C" void kernel_launch(void* const* d_in, const int* in_sizes, int n_in,
                              void* d_out, int out_size) {
    const int* nt = (const int*)d_in[0];
    const float* pos = (const float*)d_in[1];
    const int* ei = (const int*)d_in[2];
    const float* ea = (const float*)d_in[3];
    const int* batch = (const int*)d_in[4];
    const float* emb = (const float*)d_in[5];
    const float* ew1 = (const float*)d_in[6];
    const float* eb1 = (const float*)d_in[7];
    const float* ew2 = (const float*)d_in[8];
    const float* eb2 = (const float*)d_in[9];
    const float* cw1 = (const float*)d_in[10];
    const float* cb1 = (const float*)d_in[11];
    const float* cw2 = (const float*)d_in[12];
    const float* cb2 = (const float*)d_in[13];
    const float* nw1 = (const float*)d_in[14];
    const float* nb1 = (const float*)d_in[15];
    const float* nw2 = (const float*)d_in[16];
    const float* nb2 = (const float*)d_in[17];
    const float* prew = (const float*)d_in[18];
    const float* preb = (const float*)d_in[19];
    const float* qw = (const float*)d_in[20];
    const float* pw1 = (const float*)d_in[21];
    const float* pb1 = (const float*)d_in[22];
    const float* pw2 = (const float*)d_in[23];
    const float* pb2 = (const float*)d_in[24];
    float* out = (float*)d_out;

    cudaFuncSetAttribute(edge_kernel, cudaFuncAttributeMaxDynamicSharedMemorySize, EDGE_SMEM_B);
    cudaFuncSetAttribute(node_kernel, cudaFuncAttributeMaxDynamicSharedMemorySize, NODE_SMEM_B);

    init_kernel<<<512, 256>>>(nt, emb, pos);
    deg_kernel<<<512, 256>>>(ei);
    for (int l = 0; l < NL; l++) {
        edge_kernel<<<148, 768, EDGE_SMEM_B>>>(ei, ea, ew1, eb1, ew2, eb2,
                                               cw1, cb1, cw2, cb2, l);
        node_kernel<<<148, 512, NODE_SMEM_B>>>(nw1, nb1, nw2, nb2, l);
    }
    pool_zero_kernel<<<64, 256>>>();
    pool_kernel<<<512, 256>>>(batch);
    final_kernel<<<1, 128>>>(prew, preb, qw, pw1, pb1, pw2, pb2, out);
}